// round 1
// baseline (speedup 1.0000x reference)
#include <cuda_runtime.h>
#include <math.h>

// ---------------------------------------------------------------------------
// Net_47132971107101: fake-quant CNN forward
//   x[B,1,28,28] -> conv3x3(w1q, ternary, /2 folded) -> pooled 2-bit a1 {0..3}
//   -> conv3x3 via dp4a on packed int8 -> pooled 2-bit a2 {0..3}
//   -> FC via dp4a -> out[B,10] * 2*sf
// One 224-thread block per image. Stages 2-3 are exact integer arithmetic.
// ---------------------------------------------------------------------------

__device__ float g_w1s[36];     // 4 outch x 9 taps, quantized * s1 * 0.5
__device__ int   g_w2pack[36];  // 4 outch x 9 taps, 4 in-ch int8 per word
__device__ int   g_wfpack[490]; // 10 outputs x 49 words, 4 flatten-idx int8 per word
__device__ float g_s2v;         // s2
__device__ float g_sf2;         // 2*sf

__global__ void prep_kernel(const float* __restrict__ w1,
                            const float* __restrict__ w2,
                            const float* __restrict__ wf) {
    __shared__ float red[256];
    const int t = threadIdx.x;

    // s1 = max|w1| (36)
    float m = 0.f;
    for (int i = t; i < 36; i += 256) m = fmaxf(m, fabsf(w1[i]));
    red[t] = m; __syncthreads();
    for (int s = 128; s > 0; s >>= 1) { if (t < s) red[t] = fmaxf(red[t], red[t+s]); __syncthreads(); }
    const float s1 = red[0]; __syncthreads();

    // s2 = max|w2| (144)
    m = 0.f;
    for (int i = t; i < 144; i += 256) m = fmaxf(m, fabsf(w2[i]));
    red[t] = m; __syncthreads();
    for (int s = 128; s > 0; s >>= 1) { if (t < s) red[t] = fmaxf(red[t], red[t+s]); __syncthreads(); }
    const float s2 = red[0]; __syncthreads();

    // sf = max|wf| (1960)
    m = 0.f;
    for (int i = t; i < 1960; i += 256) m = fmaxf(m, fabsf(wf[i]));
    red[t] = m; __syncthreads();
    for (int s = 128; s > 0; s >>= 1) { if (t < s) red[t] = fmaxf(red[t], red[t+s]); __syncthreads(); }
    const float sf = red[0];

    // w1: quantize ternary, fold scale*0.5 so conv1 output is h/2 directly
    if (t < 36) {
        float q = fminf(fmaxf(rintf(w1[t] / s1), -1.f), 1.f);
        g_w1s[t] = 0.5f * s1 * q;
    }
    // w2: pack 4 input channels per (outch, tap) word as signed int8
    if (t < 36) {
        const int o = t / 9, tap = t % 9;
        int pack = 0;
        #pragma unroll
        for (int i = 0; i < 4; i++) {
            float q = fminf(fmaxf(rintf(w2[o*36 + i*9 + tap] / s2), -1.f), 1.f);
            pack |= (((int)q) & 0xFF) << (8 * i);
        }
        g_w2pack[t] = pack;
    }
    // wf: pack 4 consecutive flatten indices per word
    for (int i = t; i < 490; i += 256) {
        const int o = i / 49, w = i % 49;
        int pack = 0;
        #pragma unroll
        for (int j = 0; j < 4; j++) {
            float q = fminf(fmaxf(rintf(wf[o*196 + w*4 + j] / sf), -1.f), 1.f);
            pack |= (((int)q) & 0xFF) << (8 * j);
        }
        g_wfpack[i] = pack;
    }
    if (t == 0) { g_s2v = s2; g_sf2 = 2.f * sf; }
}

#define TPB 224

__global__ void __launch_bounds__(TPB)
net_kernel(const float* __restrict__ x, float* __restrict__ out) {
    __shared__ float img[30 * 33];   // zero-padded 28x28 image (stride 33)
    __shared__ int   a1p[16 * 16];   // padded 14x14, 4 channels packed as bytes {0..3}
    __shared__ int   a2w[49];        // 196 bytes of a2 {0..3}, flatten order == thread id
    __shared__ float s_w1[36];
    __shared__ int   s_w2[36];
    __shared__ int   s_wf[490];

    const int t = threadIdx.x;
    const long long b = blockIdx.x;

    if (t < 36) { s_w1[t] = g_w1s[t]; s_w2[t] = g_w2pack[t]; }
    for (int i = t; i < 490; i += TPB) s_wf[i] = g_wfpack[i];
    for (int i = t; i < 30*33; i += TPB) img[i] = 0.f;
    for (int i = t; i < 256; i += TPB) a1p[i] = 0;
    __syncthreads();

    // ---- load image (784 floats = 196 float4, 28%4==0 so each lies in a row)
    const float4* xin = (const float4*)(x + b * 784);
    if (t < 196) {
        float4 v = xin[t];
        const int p = t * 4;
        const int y = p / 28, c = p % 28;
        float* d = &img[(y + 1) * 33 + (c + 1)];
        d[0] = v.x; d[1] = v.y; d[2] = v.z; d[3] = v.w;
    }
    __syncthreads();

    // ---- conv1 (fp32) + pool + 2-bit quant: thread t -> pooled pos (py,px), all 4 ch
    if (t < 196) {
        const int py = t / 14, px = t % 14;
        float p[4][4];
        const float* base = &img[(2 * py) * 33 + 2 * px];
        #pragma unroll
        for (int r = 0; r < 4; r++)
            #pragma unroll
            for (int c = 0; c < 4; c++)
                p[r][c] = base[r * 33 + c];
        int packv = 0;
        #pragma unroll
        for (int ch = 0; ch < 4; ch++) {
            float w[9];
            #pragma unroll
            for (int k = 0; k < 9; k++) w[k] = s_w1[ch * 9 + k];
            float mx = -1e30f;
            #pragma unroll
            for (int wy = 0; wy < 2; wy++)
                #pragma unroll
                for (int wx = 0; wx < 2; wx++) {
                    float acc = 0.f;
                    #pragma unroll
                    for (int ky = 0; ky < 3; ky++)
                        #pragma unroll
                        for (int kx = 0; kx < 3; kx++)
                            acc = fmaf(w[ky * 3 + kx], p[wy + ky][wx + kx], acc);
                    mx = fmaxf(mx, acc);
                }
            // mx is h/2 (scale folded); a = clamp(rint(mx), 0, 3)
            const int a = (int)fminf(fmaxf(rintf(mx), 0.f), 3.f);
            packv |= a << (8 * ch);
        }
        a1p[(py + 1) * 16 + (px + 1)] = packv;
    }
    __syncthreads();

    // ---- conv2 (dp4a) + pool + 2-bit quant: thread t -> (ch, py, px) of 4x7x7
    const float s2v = g_s2v;
    if (t < 196) {
        const int ch = t / 49, pp = t % 49, py = pp / 7, px = pp % 7;
        int q[4][4];
        const int* base = &a1p[(2 * py) * 16 + 2 * px];
        #pragma unroll
        for (int r = 0; r < 4; r++)
            #pragma unroll
            for (int c = 0; c < 4; c++)
                q[r][c] = base[r * 16 + c];
        int wv[9];
        #pragma unroll
        for (int k = 0; k < 9; k++) wv[k] = s_w2[ch * 9 + k];
        float mx = -1e30f;
        #pragma unroll
        for (int wy = 0; wy < 2; wy++)
            #pragma unroll
            for (int wx = 0; wx < 2; wx++) {
                int acc = 0;
                #pragma unroll
                for (int ky = 0; ky < 3; ky++)
                    #pragma unroll
                    for (int kx = 0; kx < 3; kx++)
                        acc = __dp4a(q[wy + ky][wx + kx], wv[ky * 3 + kx], acc);
                mx = fmaxf(mx, s2v * (float)acc);
            }
        const int a = (int)fminf(fmaxf(rintf(mx), 0.f), 3.f);
        ((unsigned char*)a2w)[t] = (unsigned char)a;  // flatten idx == t
    }
    __syncthreads();

    // ---- FC: 10 outputs, 49 dp4a each
    if (t < 10) {
        const int* w = &s_wf[t * 49];
        int acc = 0;
        #pragma unroll
        for (int i = 0; i < 49; i++) acc = __dp4a(a2w[i], w[i], acc);
        out[b * 10 + t] = g_sf2 * (float)acc;
    }
}

extern "C" void kernel_launch(void* const* d_in, const int* in_sizes, int n_in,
                              void* d_out, int out_size) {
    const float* x  = (const float*)d_in[0];
    const float* w1 = (const float*)d_in[1];
    const float* w2 = (const float*)d_in[2];
    const float* wf = (const float*)d_in[3];
    float* out = (float*)d_out;
    const int B = in_sizes[0] / 784;

    prep_kernel<<<1, 256>>>(w1, w2, wf);
    net_kernel<<<B, TPB>>>(x, out);
}

// round 5
// speedup vs baseline: 1.0720x; 1.0720x over previous
#include <cuda_runtime.h>
#include <math.h>

typedef unsigned long long ull;

// ---------------------------------------------------------------------------
// Net_47132971107101: fake-quant CNN forward
//   conv1 fp32 (packed f32x2 FMA, 2 outputs/thread) -> 2-bit a1
//   conv2 dp4a (4 channels/thread, patch loaded once) -> 2-bit a2
//   FC dp4a (spatial-major packed) -> out * 2*sf
// 2 images per 256-thread block.
// ---------------------------------------------------------------------------

__device__ float g_w1s[36];     // 4 outch x 9 taps, ternary * s1 * 0.5
__device__ int   g_w2pack[36];  // 4 outch x 9 taps, 4 in-ch int8 per word
__device__ __align__(16) int g_wfpack[492]; // 10 outs x 49 words (+pad); word pp = 4ch @ spatial pp
__device__ float g_s2v;
__device__ float g_sf2;

__global__ void prep_kernel(const float* __restrict__ w1,
                            const float* __restrict__ w2,
                            const float* __restrict__ wf) {
    __shared__ float red[256];
    const int t = threadIdx.x;

    float m = 0.f;
    for (int i = t; i < 36; i += 256) m = fmaxf(m, fabsf(w1[i]));
    red[t] = m; __syncthreads();
    for (int s = 128; s > 0; s >>= 1) { if (t < s) red[t] = fmaxf(red[t], red[t+s]); __syncthreads(); }
    const float s1 = red[0]; __syncthreads();

    m = 0.f;
    for (int i = t; i < 144; i += 256) m = fmaxf(m, fabsf(w2[i]));
    red[t] = m; __syncthreads();
    for (int s = 128; s > 0; s >>= 1) { if (t < s) red[t] = fmaxf(red[t], red[t+s]); __syncthreads(); }
    const float s2 = red[0]; __syncthreads();

    m = 0.f;
    for (int i = t; i < 1960; i += 256) m = fmaxf(m, fabsf(wf[i]));
    red[t] = m; __syncthreads();
    for (int s = 128; s > 0; s >>= 1) { if (t < s) red[t] = fmaxf(red[t], red[t+s]); __syncthreads(); }
    const float sf = red[0];

    if (t < 36) {
        float q = fminf(fmaxf(rintf(w1[t] / s1), -1.f), 1.f);
        g_w1s[t] = 0.5f * s1 * q;
    }
    if (t < 36) {
        const int o = t / 9, tap = t % 9;
        int pack = 0;
        #pragma unroll
        for (int i = 0; i < 4; i++) {
            float q = fminf(fmaxf(rintf(w2[o*36 + i*9 + tap] / s2), -1.f), 1.f);
            pack |= (((int)q) & 0xFF) << (8 * i);
        }
        g_w2pack[t] = pack;
    }
    // wf: word (o, pp) packs the 4 channel values at spatial position pp
    // (flatten index = ch*49 + pp)
    for (int i = t; i < 490; i += 256) {
        const int o = i / 49, pp = i % 49;
        int pack = 0;
        #pragma unroll
        for (int j = 0; j < 4; j++) {
            float q = fminf(fmaxf(rintf(wf[o*196 + j*49 + pp] / sf), -1.f), 1.f);
            pack |= (((int)q) & 0xFF) << (8 * j);
        }
        g_wfpack[i] = pack;
    }
    if (t < 2) g_wfpack[490 + t] = 0;  // pad
    if (t == 0) { g_s2v = s2; g_sf2 = 2.f * sf; }
}

// ---- Blackwell packed f32x2 helpers --------------------------------------
__device__ __forceinline__ ull f2pk(float lo, float hi) {
    ull r; asm("mov.b64 %0, {%1,%2};" : "=l"(r) : "f"(lo), "f"(hi)); return r;
}
__device__ __forceinline__ void f2up(ull v, float& lo, float& hi) {
    asm("mov.b64 {%0,%1}, %2;" : "=f"(lo), "=f"(hi) : "l"(v));
}
__device__ __forceinline__ ull ffma2(ull a, ull b, ull c) {
    ull d; asm("fma.rn.f32x2 %0, %1, %2, %3;" : "=l"(d) : "l"(a), "l"(b), "l"(c)); return d;
}

#define TPB 256

__global__ void __launch_bounds__(TPB)
net_kernel(const float* __restrict__ x, float* __restrict__ out) {
    __shared__ __align__(16) float img[2][30 * 34];  // zero-border padded, even stride
    __shared__ __align__(16) int   a1p[2][16 * 16];  // padded 14x14, 4ch bytes packed
    __shared__ __align__(16) int   a2w[2][52];       // 49 words: 4ch bytes @ spatial pp

    const int t = threadIdx.x;
    const int g = t >> 7;        // image within block
    const int u = t & 127;       // lane within image group
    const long long b0 = (long long)blockIdx.x * 2;

    // ---- phase 0: borders + image interior -------------------------------
    if (t < 232) {               // img borders: 116 cells per image
        int gi = t / 116, j = t % 116, y, c;
        if (j < 30)      { y = 0;          c = j; }
        else if (j < 60) { y = 29;         c = j - 30; }
        else if (j < 88) { y = j - 60 + 1; c = 0; }
        else             { y = j - 88 + 1; c = 29; }
        img[gi][y * 34 + c] = 0.f;
    }
    if (t < 120) {               // a1p borders: 60 cells per image
        int gi = t / 60, j = t % 60, y, c;
        if (j < 16)      { y = 0;          c = j; }
        else if (j < 32) { y = 15;         c = j - 16; }
        else if (j < 46) { y = j - 32 + 1; c = 0; }
        else             { y = j - 46 + 1; c = 15; }
        a1p[gi][y * 16 + c] = 0;
    }
    if (t < 6) a2w[t / 3][49 + (t % 3)] = 0;  // pad for int4 FC reads

    for (int i = t; i < 392; i += TPB) {      // 196 float4 per image
        int gi = i / 196, q = i % 196;
        float4 v = ((const float4*)(x + (b0 + gi) * 784))[q];
        int p = q * 4, y = p / 28, c = p % 28;
        float* d = &img[gi][(y + 1) * 34 + (c + 1)];
        d[0] = v.x; d[1] = v.y; d[2] = v.z; d[3] = v.w;
    }
    __syncthreads();

    // ---- conv1 + pool + quant: thread -> (py, px-pair), all 4 channels ----
    if (u < 98) {
        const int py = u / 7, pxp = u % 7;
        const float* base = &img[g][(2 * py) * 34 + 4 * pxp];
        float2 p[4][3];
        #pragma unroll
        for (int r = 0; r < 4; r++)
            #pragma unroll
            for (int j = 0; j < 3; j++)
                p[r][j] = *(const float2*)(base + r * 34 + 2 * j);

        ull P0[4], P1[4], P2[4], X1[4], X2[4];
        #pragma unroll
        for (int r = 0; r < 4; r++) {
            P0[r] = f2pk(p[r][0].x, p[r][0].y);
            P1[r] = f2pk(p[r][1].x, p[r][1].y);
            P2[r] = f2pk(p[r][2].x, p[r][2].y);
            X1[r] = f2pk(p[r][0].y, p[r][1].x);
            X2[r] = f2pk(p[r][1].y, p[r][2].x);
        }

        int pk0 = 0, pk1 = 0;
        #pragma unroll
        for (int ch = 0; ch < 4; ch++) {
            ull wp[9];
            #pragma unroll
            for (int k = 0; k < 9; k++) {
                float w = __ldg(&g_w1s[ch * 9 + k]);
                wp[k] = f2pk(w, w);
            }
            ull aA[2], aB[2];
            #pragma unroll
            for (int wy = 0; wy < 2; wy++) {
                ull a = 0ull, bb = 0ull;
                #pragma unroll
                for (int ky = 0; ky < 3; ky++) {
                    const int r = wy + ky;
                    a  = ffma2(P0[r], wp[ky*3 + 0], a);
                    a  = ffma2(X1[r], wp[ky*3 + 1], a);
                    a  = ffma2(P1[r], wp[ky*3 + 2], a);
                    bb = ffma2(P1[r], wp[ky*3 + 0], bb);
                    bb = ffma2(X2[r], wp[ky*3 + 1], bb);
                    bb = ffma2(P2[r], wp[ky*3 + 2], bb);
                }
                aA[wy] = a; aB[wy] = bb;
            }
            float l0, h0, l1, h1;
            f2up(aA[0], l0, h0); f2up(aA[1], l1, h1);
            const float m0 = fmaxf(fmaxf(l0, h0), fmaxf(l1, h1));
            f2up(aB[0], l0, h0); f2up(aB[1], l1, h1);
            const float m1 = fmaxf(fmaxf(l0, h0), fmaxf(l1, h1));
            const int a0 = (int)fminf(fmaxf(rintf(m0), 0.f), 3.f);
            const int a1v = (int)fminf(fmaxf(rintf(m1), 0.f), 3.f);
            pk0 |= a0 << (8 * ch);
            pk1 |= a1v << (8 * ch);
        }
        const int col = 2 * pxp + 1;
        a1p[g][(py + 1) * 16 + col]     = pk0;
        a1p[g][(py + 1) * 16 + col + 1] = pk1;
    }
    __syncthreads();

    // ---- conv2 + pool + quant: thread -> spatial pp, all 4 channels -------
    if (u < 49) {
        const int py = u / 7, px = u % 7;
        int q[4][4];
        #pragma unroll
        for (int r = 0; r < 4; r++) {
            int2 v0 = *(const int2*)&a1p[g][(2 * py + r) * 16 + 2 * px];
            int2 v1 = *(const int2*)&a1p[g][(2 * py + r) * 16 + 2 * px + 2];
            q[r][0] = v0.x; q[r][1] = v0.y; q[r][2] = v1.x; q[r][3] = v1.y;
        }
        const float s2v = g_s2v;
        int packo = 0;
        #pragma unroll
        for (int ch = 0; ch < 4; ch++) {
            int wv[9];
            #pragma unroll
            for (int k = 0; k < 9; k++) wv[k] = __ldg(&g_w2pack[ch * 9 + k]);
            int mx = -2147483647;
            #pragma unroll
            for (int wy = 0; wy < 2; wy++)
                #pragma unroll
                for (int wx = 0; wx < 2; wx++) {
                    int acc = 0;
                    #pragma unroll
                    for (int ky = 0; ky < 3; ky++)
                        #pragma unroll
                        for (int kx = 0; kx < 3; kx++)
                            acc = __dp4a(q[wy + ky][wx + kx], wv[ky * 3 + kx], acc);
                    mx = max(mx, acc);
                }
            const int a = (int)fminf(fmaxf(rintf(s2v * (float)mx), 0.f), 3.f);
            packo |= a << (8 * ch);
        }
        a2w[g][u] = packo;  // spatial-major word, matches g_wfpack layout
    }
    __syncthreads();

    // ---- FC: 10 outputs x 49 dp4a ----------------------------------------
    if (u < 10) {
        int acc = 0;
        const int* wf = &g_wfpack[u * 49];
        #pragma unroll
        for (int j = 0; j < 12; j++) {
            int4 va = *(const int4*)&a2w[g][4 * j];
            acc = __dp4a(va.x, __ldg(wf + 4*j + 0), acc);
            acc = __dp4a(va.y, __ldg(wf + 4*j + 1), acc);
            acc = __dp4a(va.z, __ldg(wf + 4*j + 2), acc);
            acc = __dp4a(va.w, __ldg(wf + 4*j + 3), acc);
        }
        acc = __dp4a(a2w[g][48], __ldg(wf + 48), acc);
        out[(b0 + g) * 10 + u] = g_sf2 * (float)acc;
    }
}

extern "C" void kernel_launch(void* const* d_in, const int* in_sizes, int n_in,
                              void* d_out, int out_size) {
    const float* x  = (const float*)d_in[0];
    const float* w1 = (const float*)d_in[1];
    const float* w2 = (const float*)d_in[2];
    const float* wf = (const float*)d_in[3];
    float* out = (float*)d_out;
    const int B = in_sizes[0] / 784;

    prep_kernel<<<1, 256>>>(w1, w2, wf);
    net_kernel<<<B / 2, TPB>>>(x, out);
}